// round 17
// baseline (speedup 1.0000x reference)
#include <cuda_runtime.h>
#include <cuda_fp16.h>
#include <cstdint>

#define NN 50000
#define NE 800000
#define NG 64
#define MAXF 128
#define SCAN_BLK 256
#define NBLK ((NN + SCAN_BLK - 1) / SCAN_BLK)   // 196

typedef unsigned long long ull;

// ---------------- scratch (device globals; no runtime allocation) ----------------
__device__ __align__(16) float g_bufA[NN * MAXF];
__device__ __align__(16) float g_h[NN * MAXF];        // fp32 H (layer 3)
__device__ __align__(16) __half g_h16[NN * MAXF];     // fp16 H (layers 1,2)
__device__ __align__(16) ull g_sd[NE];   // packed (src | dst<<32)
__device__ ull   g_edge[NE];             // CSR-permuted (src | norm<<32)
__device__ ull   g_dc[NN];               // packed (count<<32 | deg_fixedpoint)
__device__ int   g_count[NN];
__device__ int   g_rowptr[NN];           // bucket base; after fill: bucket END
__device__ float g_dinv[NN];
__device__ float g_invdeg[NN];
__device__ __align__(16) float g_pool[NG * 32];
__device__ float g_cnt[NG];
__device__ unsigned int g_maxbits;       // memset to 0
__device__ int g_total;                  // memset to 0
__device__ unsigned int g_oddOr;         // self-initialized by k_detect

#define DEG_SCALE 16777216.0f
#define DEG_INV   (1.0f / 16777216.0f)

// ---------------- packed f32x2 helpers ----------------
__device__ __forceinline__ ull pack2(float x, float y) {
    ull r; asm("mov.b64 %0, {%1,%2};" : "=l"(r) : "f"(x), "f"(y)); return r;
}
__device__ __forceinline__ void unpack2(ull v, float& x, float& y) {
    asm("mov.b64 {%0,%1}, %2;" : "=f"(x), "=f"(y) : "l"(v));
}
__device__ __forceinline__ void ffma2(ull& c, ull a, ull b) {
    asm("fma.rn.f32x2 %0, %1, %2, %0;" : "+l"(c) : "l"(a), "l"(b));
}

// ---------------- dtype detection: single block, self-initializing ----------------
__global__ void k_detect(const unsigned int* __restrict__ ei32) {
    if (threadIdx.x == 0) g_oddOr = 0u;
    __syncthreads();
    unsigned int v = 0;
    for (int t = threadIdx.x; t < 8192; t += blockDim.x)
        v |= ei32[2 * t + 1];
#pragma unroll
    for (int o = 16; o; o >>= 1) v |= __shfl_xor_sync(0xffffffffu, v, o);
    if ((threadIdx.x & 31) == 0 && v) atomicOr(&g_oddOr, v);
}

// ---------------- fused per-edge pass (2 edges/thread): decode, max(ea), packed deg+count ----------------
__global__ void k_prep(const void* __restrict__ ei, const float* __restrict__ ea) {
    bool is64 = (g_oddOr == 0u);
    int p = blockIdx.x * blockDim.x + threadIdx.x;   // pair index
    if (p >= NE / 2) return;
    int e = p * 2;
    int s0, d0, s1, d1;
    if (is64) {
        const longlong2* p64 = (const longlong2*)ei;
        longlong2 sv = p64[p];                 // src[e], src[e+1]
        longlong2 dv = p64[NE / 2 + p];        // dst[e], dst[e+1]
        s0 = (int)sv.x; s1 = (int)sv.y;
        d0 = (int)dv.x; d1 = (int)dv.y;
    } else {
        const int2* p32 = (const int2*)ei;
        int2 sv = p32[p];
        int2 dv = p32[NE / 2 + p];
        s0 = sv.x; s1 = sv.y;
        d0 = dv.x; d1 = dv.y;
    }
    float2 a = *(const float2*)(ea + e);
    ull sd0 = (ull)(unsigned int)s0 | ((ull)(unsigned int)d0 << 32);
    ull sd1 = (ull)(unsigned int)s1 | ((ull)(unsigned int)d1 << 32);
    *(ulonglong2*)&g_sd[e] = make_ulonglong2(sd0, sd1);

    float m = fmaxf(a.x, a.y);
    atomicAdd(&g_dc[d0], ((ull)1 << 32) | (ull)__float2uint_rn(a.x * DEG_SCALE));
    atomicAdd(&g_dc[d1], ((ull)1 << 32) | (ull)__float2uint_rn(a.y * DEG_SCALE));
#pragma unroll
    for (int o = 16; o; o >>= 1) m = fmaxf(m, __shfl_xor_sync(0xffffffffu, m, o));
    if ((threadIdx.x & 31) == 0) atomicMax(&g_maxbits, __float_as_uint(m));
}

// ---------------- single-pass bucket allocation + node factors ----------------
__global__ void k_scanA() {
    __shared__ int wsum[SCAN_BLK / 32];
    __shared__ int sbase;
    int i = blockIdx.x * SCAN_BLK + threadIdx.x;
    ull dc = (i < NN) ? g_dc[i] : 0ull;
    int c = (int)(dc >> 32);
    int lane = threadIdx.x & 31, wid = threadIdx.x >> 5;
    int v = c;
#pragma unroll
    for (int o = 1; o < 32; o <<= 1) {
        int u = __shfl_up_sync(0xffffffffu, v, o);
        if (lane >= o) v += u;
    }
    if (lane == 31) wsum[wid] = v;
    __syncthreads();
    if (wid == 0) {
        int w = (lane < SCAN_BLK / 32) ? wsum[lane] : 0;
#pragma unroll
        for (int o = 1; o < SCAN_BLK / 32; o <<= 1) {
            int u = __shfl_up_sync(0xffffffffu, w, o);
            if (lane >= o) w += u;
        }
        if (lane < SCAN_BLK / 32) wsum[lane] = w;
    }
    __syncthreads();
    if (threadIdx.x == 0) sbase = atomicAdd(&g_total, wsum[SCAN_BLK / 32 - 1]);
    __syncthreads();
    if (i < NN) {
        int excl = v - c + (wid > 0 ? wsum[wid - 1] : 0);
        g_rowptr[i] = sbase + excl;
        g_count[i] = c;
        float degraw = (float)(unsigned int)(dc & 0xffffffffu) * DEG_INV;
        float invmax = 1.f / __uint_as_float(g_maxbits);
        float d = fmaf(degraw, invmax, 1.f);
        g_dinv[i] = rsqrtf(d);
        g_invdeg[i] = 1.f / d;
    }
}

// ---------------- fill CSR: slot claimed by post-incrementing rowptr ----------------
__global__ void k_fill(const float* __restrict__ ea) {
    int e = blockIdx.x * blockDim.x + threadIdx.x;
    if (e >= NE) return;
    ull sd = g_sd[e];
    int s = (int)(unsigned int)sd;
    int d = (int)(sd >> 32);
    float invmax = 1.f / __uint_as_float(g_maxbits);
    float norm = g_dinv[s] * (ea[e] * invmax) * g_dinv[d];
    int pos = atomicAdd(&g_rowptr[d], 1);
    g_edge[pos] = (ull)(unsigned int)s | ((ull)__float_as_uint(norm) << 32);
}

// ---------------- 128xBN-tiled fp32 GEMM (champion kernel) ----------------
template <int BN, int TN, int STOREH>
__global__ void k_gemm(const float* __restrict__ Aext, int useBufA,
                       const float* __restrict__ W, int M, int K, int reluIn) {
    __shared__ float As[16][132];
    __shared__ float Bs[16][BN + 4];
    const float* A = useBufA ? g_bufA : Aext;

    int tid = threadIdx.x;
    int tr = tid >> 4;
    int tc = tid & 15;
    int rowBase = blockIdx.y * 128;

    ull acc2[8][TN / 2];
#pragma unroll
    for (int i = 0; i < 8; i++)
#pragma unroll
        for (int j = 0; j < TN / 2; j++) acc2[i][j] = 0ull;

    for (int kt = 0; kt < K; kt += 16) {
#pragma unroll
        for (int idx = tid; idx < 512; idx += 256) {
            int r = idx >> 2;
            int c4 = (idx & 3) * 4;
            int ar = rowBase + r;
            float4 v = make_float4(0.f, 0.f, 0.f, 0.f);
            if (ar < M) v = *(const float4*)(A + (size_t)ar * K + kt + c4);
            if (reluIn) {
                v.x = fmaxf(v.x, 0.f); v.y = fmaxf(v.y, 0.f);
                v.z = fmaxf(v.z, 0.f); v.w = fmaxf(v.w, 0.f);
            }
            As[c4 + 0][r] = v.x; As[c4 + 1][r] = v.y;
            As[c4 + 2][r] = v.z; As[c4 + 3][r] = v.w;
        }
        constexpr int F4R = BN / 4;
#pragma unroll
        for (int idx = tid; idx < 16 * F4R; idx += 256) {
            int r = idx / F4R;
            int c = (idx % F4R) * 4;
            float4 v = *(const float4*)(W + (size_t)(kt + r) * BN + c);
            *(float4*)&Bs[r][c] = v;
        }
        __syncthreads();

#pragma unroll
        for (int kk = 0; kk < 16; kk++) {
            float a[8];
            *(float4*)&a[0] = *(const float4*)&As[kk][tr * 8];
            *(float4*)&a[4] = *(const float4*)&As[kk][tr * 8 + 4];
            ull bp[TN / 2];
#pragma unroll
            for (int j = 0; j < TN / 2; j++)
                bp[j] = *(const ull*)&Bs[kk][tc * TN + 2 * j];
#pragma unroll
            for (int i = 0; i < 8; i++) {
                ull aa = pack2(a[i], a[i]);
#pragma unroll
                for (int j = 0; j < TN / 2; j++) ffma2(acc2[i][j], aa, bp[j]);
            }
        }
        __syncthreads();
    }

#pragma unroll
    for (int i = 0; i < 8; i++) {
        int r = rowBase + tr * 8 + i;
        if (r >= M) continue;
        float o[TN];
#pragma unroll
        for (int j = 0; j < TN / 2; j++) unpack2(acc2[i][j], o[2 * j], o[2 * j + 1]);
        if (STOREH) {
            __half hh[TN];
#pragma unroll
            for (int j = 0; j < TN; j++) hh[j] = __float2half_rn(o[j]);
            char* dst = (char*)(g_h16 + (size_t)r * BN + tc * TN);
            if (TN == 8)      *(uint4*)dst = *(uint4*)hh;
            else if (TN == 4) *(uint2*)dst = *(uint2*)hh;
        } else {
            float* dst = g_h + (size_t)r * BN + tc * TN;
            if (TN == 8) {
                *(float4*)dst = *(float4*)&o[0];
                *(float4*)(dst + 4) = *(float4*)&o[4];
            } else if (TN == 4) {
                *(float4*)dst = *(float4*)&o[0];
            } else {
                *(float2*)dst = *(float2*)&o[0];
            }
        }
    }
}

// ---------------- fp16 gather (unroll 8): AGG = H16[n]*invdeg + bias + sum norm*H16[src] ----------------
template <int VEC, int SHIFT>
__global__ void k_gather16(const float* __restrict__ bias) {
    int t = blockIdx.x * blockDim.x + threadIdx.x;
    if (t >= NN * VEC) return;
    int n = t >> SHIFT;
    int j = t & (VEC - 1);
    int end = g_rowptr[n];
    int beg = end - g_count[n];
    const uint4* __restrict__ H = (const uint4*)g_h16;
    const ull* __restrict__ edge = g_edge;

    float acc[8];
    {
        float id = g_invdeg[n];
        uint4 hv = H[(size_t)n * VEC + j];
        const __half2* h2 = (const __half2*)&hv;
        const float* b = bias + j * 8;
#pragma unroll
        for (int q = 0; q < 4; q++) {
            float2 f = __half22float2(h2[q]);
            acc[2 * q + 0] = fmaf(f.x, id, b[2 * q + 0]);
            acc[2 * q + 1] = fmaf(f.y, id, b[2 * q + 1]);
        }
    }

    int k = beg;
    for (; k + 8 <= end; k += 8) {
        ull ew[8];
        uint4 vv[8];
#pragma unroll
        for (int u = 0; u < 8; u++) ew[u] = edge[k + u];
#pragma unroll
        for (int u = 0; u < 8; u++) vv[u] = H[(size_t)(unsigned int)ew[u] * VEC + j];
#pragma unroll
        for (int u = 0; u < 8; u++) {
            float nm = __uint_as_float((unsigned int)(ew[u] >> 32));
            const __half2* pp = (const __half2*)&vv[u];
#pragma unroll
            for (int q = 0; q < 4; q++) {
                float2 f = __half22float2(pp[q]);
                acc[2 * q + 0] = fmaf(nm, f.x, acc[2 * q + 0]);
                acc[2 * q + 1] = fmaf(nm, f.y, acc[2 * q + 1]);
            }
        }
    }
    for (; k + 4 <= end; k += 4) {
        ull ew[4];
        uint4 vv[4];
#pragma unroll
        for (int u = 0; u < 4; u++) ew[u] = edge[k + u];
#pragma unroll
        for (int u = 0; u < 4; u++) vv[u] = H[(size_t)(unsigned int)ew[u] * VEC + j];
#pragma unroll
        for (int u = 0; u < 4; u++) {
            float nm = __uint_as_float((unsigned int)(ew[u] >> 32));
            const __half2* pp = (const __half2*)&vv[u];
#pragma unroll
            for (int q = 0; q < 4; q++) {
                float2 f = __half22float2(pp[q]);
                acc[2 * q + 0] = fmaf(nm, f.x, acc[2 * q + 0]);
                acc[2 * q + 1] = fmaf(nm, f.y, acc[2 * q + 1]);
            }
        }
    }
    for (; k < end; k++) {
        ull e0 = edge[k];
        float nm = __uint_as_float((unsigned int)(e0 >> 32));
        uint4 v0 = H[(size_t)(unsigned int)e0 * VEC + j];
        const __half2* p0 = (const __half2*)&v0;
#pragma unroll
        for (int q = 0; q < 4; q++) {
            float2 f0 = __half22float2(p0[q]);
            acc[2 * q + 0] = fmaf(nm, f0.x, acc[2 * q + 0]);
            acc[2 * q + 1] = fmaf(nm, f0.y, acc[2 * q + 1]);
        }
    }

    float* dst = g_bufA + ((size_t)n * VEC + j) * 8;
    *(float4*)dst = *(float4*)&acc[0];
    *(float4*)(dst + 4) = *(float4*)&acc[4];
}

// ---------------- layer-3 gather (fp32 H) fused with relu + mean-pool ----------------
__global__ void k_gather_pool(const float* __restrict__ bias,
                              const void* __restrict__ batch) {
    int t = blockIdx.x * blockDim.x + threadIdx.x;
    if (t >= NN * 8) return;
    int n = t >> 3;
    int j = t & 7;
    int end = g_rowptr[n];
    int beg = end - g_count[n];
    const float4* __restrict__ H4 = (const float4*)g_h;
    const ull* __restrict__ edge = g_edge;

    float id = g_invdeg[n];
    float4 b = *(const float4*)(bias + j * 4);
    float4 hv = H4[(size_t)n * 8 + j];
    float4 acc;
    acc.x = fmaf(hv.x, id, b.x);
    acc.y = fmaf(hv.y, id, b.y);
    acc.z = fmaf(hv.z, id, b.z);
    acc.w = fmaf(hv.w, id, b.w);

    int k = beg;
    for (; k + 4 <= end; k += 4) {
        ull e0 = edge[k], e1 = edge[k + 1], e2 = edge[k + 2], e3 = edge[k + 3];
        float n0 = __uint_as_float((unsigned int)(e0 >> 32));
        float n1 = __uint_as_float((unsigned int)(e1 >> 32));
        float n2 = __uint_as_float((unsigned int)(e2 >> 32));
        float n3 = __uint_as_float((unsigned int)(e3 >> 32));
        float4 v0 = H4[(size_t)(unsigned int)e0 * 8 + j];
        float4 v1 = H4[(size_t)(unsigned int)e1 * 8 + j];
        float4 v2 = H4[(size_t)(unsigned int)e2 * 8 + j];
        float4 v3 = H4[(size_t)(unsigned int)e3 * 8 + j];
        acc.x = fmaf(n0, v0.x, acc.x); acc.y = fmaf(n0, v0.y, acc.y);
        acc.z = fmaf(n0, v0.z, acc.z); acc.w = fmaf(n0, v0.w, acc.w);
        acc.x = fmaf(n1, v1.x, acc.x); acc.y = fmaf(n1, v1.y, acc.y);
        acc.z = fmaf(n1, v1.z, acc.z); acc.w = fmaf(n1, v1.w, acc.w);
        acc.x = fmaf(n2, v2.x, acc.x); acc.y = fmaf(n2, v2.y, acc.y);
        acc.z = fmaf(n2, v2.z, acc.z); acc.w = fmaf(n2, v2.w, acc.w);
        acc.x = fmaf(n3, v3.x, acc.x); acc.y = fmaf(n3, v3.y, acc.y);
        acc.z = fmaf(n3, v3.z, acc.z); acc.w = fmaf(n3, v3.w, acc.w);
    }
    for (; k < end; k++) {
        ull e0 = edge[k];
        float nm = __uint_as_float((unsigned int)(e0 >> 32));
        float4 v = H4[(size_t)(unsigned int)e0 * 8 + j];
        acc.x = fmaf(nm, v.x, acc.x);
        acc.y = fmaf(nm, v.y, acc.y);
        acc.z = fmaf(nm, v.z, acc.z);
        acc.w = fmaf(nm, v.w, acc.w);
    }

    int g;
    if (g_oddOr == 0u) g = (int)((const long long*)batch)[n];
    else               g = ((const int*)batch)[n];
    float* p = &g_pool[g * 32 + j * 4];
    atomicAdd(p + 0, fmaxf(acc.x, 0.f));
    atomicAdd(p + 1, fmaxf(acc.y, 0.f));
    atomicAdd(p + 2, fmaxf(acc.z, 0.f));
    atomicAdd(p + 3, fmaxf(acc.w, 0.f));
    if (j == 0) atomicAdd(&g_cnt[g], 1.f);
}

// ---------------- head ----------------
__global__ void k_out(const float* __restrict__ Wl, const float* __restrict__ bl,
                      float* __restrict__ out) {
    __shared__ float pooled[32];
    int g = blockIdx.x;
    if (threadIdx.x < 32) {
        float c = g_cnt[g];
        pooled[threadIdx.x] = g_pool[g * 32 + threadIdx.x] / fmaxf(c, 1.f);
    }
    __syncthreads();
    int o = threadIdx.x;  // 768 threads
    float acc = bl[o];
#pragma unroll
    for (int c = 0; c < 32; c++) acc = fmaf(pooled[c], Wl[c * 768 + o], acc);
    out[(size_t)g * 768 + o] = acc;
}

// ---------------- launch ----------------
extern "C" void kernel_launch(void* const* d_in, const int* in_sizes, int n_in,
                              void* d_out, int out_size) {
    const float* x = (const float*)d_in[0];
    const void* ei = d_in[1];
    const float* ea = (const float*)d_in[2];
    const void* batch = d_in[3];
    const float* W1 = (const float*)d_in[4];
    const float* b1 = (const float*)d_in[5];
    const float* W2 = (const float*)d_in[6];
    const float* b2 = (const float*)d_in[7];
    const float* W3 = (const float*)d_in[8];
    const float* b3 = (const float*)d_in[9];
    const float* Wl = (const float*)d_in[10];
    const float* bl = (const float*)d_in[11];
    float* out = (float*)d_out;

    static cudaStream_t s2 = nullptr, s3 = nullptr;
    static cudaEvent_t evFork = nullptr, evJoin = nullptr, evInit = nullptr;
    static void *pDC = nullptr, *pPool = nullptr, *pCnt = nullptr,
                *pMax = nullptr, *pTot = nullptr;
    if (!s2) {
        cudaStreamCreateWithFlags(&s2, cudaStreamNonBlocking);
        cudaStreamCreateWithFlags(&s3, cudaStreamNonBlocking);
        cudaEventCreateWithFlags(&evFork, cudaEventDisableTiming);
        cudaEventCreateWithFlags(&evJoin, cudaEventDisableTiming);
        cudaEventCreateWithFlags(&evInit, cudaEventDisableTiming);
        cudaGetSymbolAddress(&pDC, g_dc);
        cudaGetSymbolAddress(&pPool, g_pool);
        cudaGetSymbolAddress(&pCnt, g_cnt);
        cudaGetSymbolAddress(&pMax, g_maxbits);
        cudaGetSymbolAddress(&pTot, g_total);
    }
    cudaStream_t s0 = cudaStreamPerThread;

    cudaEventRecord(evFork, s0);

    // Side stream s2: layer-1 GEMM (depends only on x, W1) -> fp16 H.
    cudaStreamWaitEvent(s2, evFork, 0);
    {
        dim3 grid(1, (NN + 127) / 128);
        k_gemm<128, 8, 1><<<grid, 256, 0, s2>>>(x, 0, W1, NN, 128, /*relu=*/0);
        cudaEventRecord(evJoin, s2);
    }

    // Side stream s3: zero accumulators via memsets.
    cudaStreamWaitEvent(s3, evFork, 0);
    cudaMemsetAsync(pDC, 0, NN * sizeof(ull), s3);
    cudaMemsetAsync(pPool, 0, NG * 32 * sizeof(float), s3);
    cudaMemsetAsync(pCnt, 0, NG * sizeof(float), s3);
    cudaMemsetAsync(pMax, 0, sizeof(unsigned int), s3);
    cudaMemsetAsync(pTot, 0, sizeof(int), s3);
    cudaEventRecord(evInit, s3);

    // Main stream: detection (self-initializing) runs concurrently with memsets.
    k_detect<<<1, 256, 0, s0>>>((const unsigned int*)ei);
    cudaStreamWaitEvent(s0, evInit, 0);
    k_prep<<<(NE / 2 + 255) / 256, 256, 0, s0>>>(ei, ea);
    k_scanA<<<NBLK, SCAN_BLK, 0, s0>>>();
    k_fill<<<(NE + 255) / 256, 256, 0, s0>>>(ea);

    // Join: gather-1 needs both H16 (s2) and CSR (s0).
    cudaStreamWaitEvent(s0, evJoin, 0);
    k_gather16<16, 4><<<(NN * 16 + 255) / 256, 256, 0, s0>>>(b1);

    // Layer 2: relu(bufA) @ W2 -> fp16 H; fp16 gather -> bufA
    {
        dim3 grid(1, (NN + 127) / 128);
        k_gemm<64, 4, 1><<<grid, 256, 0, s0>>>(nullptr, 1, W2, NN, 128, /*relu=*/1);
        k_gather16<8, 3><<<(NN * 8 + 255) / 256, 256, 0, s0>>>(b2);
    }
    // Layer 3: relu(bufA) @ W3 -> fp32 H; fp32 gather fused with pool
    {
        dim3 grid(1, (NN + 127) / 128);
        k_gemm<32, 2, 0><<<grid, 256, 0, s0>>>(nullptr, 1, W3, NN, 64, /*relu=*/1);
        k_gather_pool<<<(NN * 8 + 255) / 256, 256, 0, s0>>>(b3, batch);
    }
    k_out<<<NG, 768, 0, s0>>>(Wl, bl, out);
}